// round 14
// baseline (speedup 1.0000x reference)
#include <cuda_runtime.h>

// Problem constants (from reference): B=4096, D=512, K=10, L=256, V=80
#define BQ 4096
#define DD 512
#define KK 10
#define LL 256
#define VV 80

// Scratch: alpha[0:10], beta[10:20], kappa[20:30] per batch row.
__device__ float g_abk[BQ * 30];

// exp(e) for e <= 0 (clipped upstream), FMA-pipe only (no MUFU).
__device__ __forceinline__ float fast_exp_neg(float e) {
    float t = e * 1.44269504088896341f;
    int i = __float2int_rd(t);
    float f = t - (float)i;
    float p = 1.5403530393381610e-4f;
    p = fmaf(p, f, 1.3333558146428443e-3f);
    p = fmaf(p, f, 9.6181291076284772e-3f);
    p = fmaf(p, f, 5.5504108664821580e-2f);
    p = fmaf(p, f, 2.4022650695910071e-1f);
    p = fmaf(p, f, 6.9314718055994531e-1f);
    p = fmaf(p, f, 1.0f);
    return p * __int_as_float((i + 127) << 23);
}

__device__ __forceinline__ float warp_max(float v) {
    #pragma unroll
    for (int off = 16; off > 0; off >>= 1)
        v = fmaxf(v, __shfl_xor_sync(0xffffffffu, v, off));
    return v;
}

// Kernel A: register-blocked GEMM. 128 blocks x 256 threads, 32 rows/block,
// warp owns 4 rows (acc[4]) -> per 4-d chunk: 4 W-LDS + 4 broadcast X-LDS +
// 16 FFMA (2x better FMA:LDS than the 2-row version). Stride-33 W smem keeps
// the cross-lane LDS conflict-free.
__global__ __launch_bounds__(256) void gemm_act_kernel(
    const float* __restrict__ X, const float* __restrict__ W,
    const float* __restrict__ bias, const float* __restrict__ prev_kappa,
    const float* __restrict__ kappa_scale_p, float* __restrict__ out_kappa)
{
    __shared__ float4 Xs4[32 * 32];          // 32 rows x 32 float4 = 16 KB
    __shared__ float  Wsh[128 * 33];         // 16.5 KB, stride-33 padded

    const int tid  = threadIdx.x;
    const int warp = tid >> 5;
    const int lane = tid & 31;
    const int b0   = blockIdx.x * 32;

    const float4* X4 = (const float4*)X;

    float acc[4] = {0.f, 0.f, 0.f, 0.f};

    for (int t = 0; t < 4; ++t) {
        __syncthreads();
        for (int i = tid; i < 128 * 30; i += 256) {
            int d = i / 30, j = i - d * 30;
            Wsh[d * 33 + j] = W[t * (128 * 30) + i];
        }
        for (int i = tid; i < 1024; i += 256) {
            int r = i >> 5, c = i & 31;
            Xs4[i] = X4[(size_t)(b0 + r) * 128 + t * 32 + c];
        }
        __syncthreads();

        const float4* xr0 = &Xs4[(warp * 4 + 0) * 32];
        const float4* xr1 = &Xs4[(warp * 4 + 1) * 32];
        const float4* xr2 = &Xs4[(warp * 4 + 2) * 32];
        const float4* xr3 = &Xs4[(warp * 4 + 3) * 32];

        #pragma unroll 4
        for (int c = 0; c < 32; ++c) {
            float w0 = Wsh[(4 * c + 0) * 33 + lane];
            float w1 = Wsh[(4 * c + 1) * 33 + lane];
            float w2 = Wsh[(4 * c + 2) * 33 + lane];
            float w3 = Wsh[(4 * c + 3) * 33 + lane];
            float4 x0 = xr0[c], x1 = xr1[c], x2 = xr2[c], x3 = xr3[c];
            acc[0] = fmaf(x0.x, w0, fmaf(x0.y, w1, fmaf(x0.z, w2, fmaf(x0.w, w3, acc[0]))));
            acc[1] = fmaf(x1.x, w0, fmaf(x1.y, w1, fmaf(x1.z, w2, fmaf(x1.w, w3, acc[1]))));
            acc[2] = fmaf(x2.x, w0, fmaf(x2.y, w1, fmaf(x2.z, w2, fmaf(x2.w, w3, acc[2]))));
            acc[3] = fmaf(x3.x, w0, fmaf(x3.y, w1, fmaf(x3.z, w2, fmaf(x3.w, w3, acc[3]))));
        }
    }

    if (lane < 30) {
        const float bj = bias[lane];
        const float ks = *kappa_scale_p;
        #pragma unroll
        for (int rr = 0; rr < 4; ++rr) {
            int b = b0 + warp * 4 + rr;
            float raw = acc[rr] + bj;
            float val;
            if (lane < 20) {
                val = __expf(fminf(fmaxf(raw, -8.f), 8.f));
            } else {
                float dk = __expf(fminf(fmaxf(raw + ks, -8.f), 5.f));
                val = prev_kappa[b * KK + (lane - 20)] + dk;
                out_kappa[b * KK + (lane - 20)] = val;
            }
            g_abk[b * 30 + lane] = val;
        }
    }
}

// Kernel B (R10's proven merged version): warp-per-row, analytic l_hi, bounded
// first window of 32 with prefetched rounds, rare warps (l_hi > 32, ~18%) loop
// additional 32-l windows in-warp. 1024 blocks x 128 threads.
__global__ __launch_bounds__(128) void phi_w_kernel(
    const float* __restrict__ oh, const int* __restrict__ seqlens,
    float* __restrict__ out_w)
{
    __shared__ float s_abk[4][30];
    __shared__ float s_phi[4][36];

    const int wrow = threadIdx.x >> 5;
    const int lane = threadIdx.x & 31;
    const int b    = blockIdx.x * 4 + wrow;

    const float* row = oh + (size_t)b * (LL * VV);

    // ---- front batch of independent loads ----
    float val = 0.f;
    if (lane < 30) val = g_abk[b * 30 + lane];
    const int seqlen = seqlens[b];

    float f0[8], f1[8], f2[8], h0[8], h1[8], h2[8];
    #pragma unroll
    for (int i = 0; i < 8; ++i) {            // rounds 0-1: always-valid memory
        f0[i] = row[i * VV + lane];
        f1[i] = row[i * VV + 32 + lane];
        f2[i] = (lane < 16) ? row[i * VV + 64 + lane] : 0.f;
    }
    #pragma unroll
    for (int i = 0; i < 8; ++i) {
        int l = 8 + i;
        h0[i] = row[l * VV + lane];
        h1[i] = row[l * VV + 32 + lane];
        h2[i] = (lane < 16) ? row[l * VV + 64 + lane] : 0.f;
    }

    if (lane < 30) s_abk[wrow][lane] = val;

    // params via shuffles off the single abk load (valid where lane < 10)
    const float al = val;
    const float be = __shfl_sync(0xffffffffu, val, (lane + 10) & 31);
    const float ka = __shfl_sync(0xffffffffu, val, (lane + 20) & 31);

    // ---- analytic truncation bound (hidden under the prefetch latency) ----
    float pk = 0.f;
    if (lane < 10) {
        float ustar = fminf(fmaxf(rintf(ka), 1.f), (float)seqlen);
        float d = ka - ustar;
        pk = al * __expf(fmaxf(-be * d * d, -87.f));
    }
    const float pm = warp_max(pk);
    float lk = 0.f;
    if (lane < 10) {
        float theta = pm * 1e-8f;
        float lnr = __logf(al) - __logf(theta);   // theta->0 => +inf => full length
        lk = ka + sqrtf(fmaxf(lnr, 0.f) / be);
        lk = fminf(lk, 256.f);
    }
    const float lm = warp_max(lk);
    const int l_hi  = min((int)ceilf(lm), seqlen);
    const int l_use = min(l_hi, 32);
    __syncwarp();

    // ---- phi[lane] for the first window (zero-padded beyond l_use) ----
    float ph = 0.f;
    if (lane < l_use) {
        float u = (float)(lane + 1);
        #pragma unroll
        for (int k = 0; k < KK; ++k) {
            float a  = s_abk[wrow][k];
            float bb = s_abk[wrow][10 + k];
            float kk = s_abk[wrow][20 + k];
            float dv = kk - u;
            float e  = fmaxf(-bb * dv * dv, -50.f);
            ph = fmaf(a, fast_exp_neg(e), ph);
        }
    }
    s_phi[wrow][lane] = ph;
    __syncwarp();

    float a0 = 0.f, a1 = 0.f, a2 = 0.f;

    // round 0 (l_hi >= 1 always)
    #pragma unroll
    for (int i = 0; i < 8; ++i) {
        float p = s_phi[wrow][i];
        a0 = fmaf(p, f0[i], a0); a1 = fmaf(p, f1[i], a1); a2 = fmaf(p, f2[i], a2);
    }
    if (l_use > 16) {                         // reload f <- l 16..23
        #pragma unroll
        for (int i = 0; i < 8; ++i) {
            int l = 16 + i;
            f0[i] = row[l * VV + lane];
            f1[i] = row[l * VV + 32 + lane];
            f2[i] = (lane < 16) ? row[l * VV + 64 + lane] : 0.f;
        }
    }
    if (l_use > 8) {                          // round 1
        #pragma unroll
        for (int i = 0; i < 8; ++i) {
            float p = s_phi[wrow][8 + i];
            a0 = fmaf(p, h0[i], a0); a1 = fmaf(p, h1[i], a1); a2 = fmaf(p, h2[i], a2);
        }
    }
    if (l_use > 24) {                         // reload h <- l 24..31
        #pragma unroll
        for (int i = 0; i < 8; ++i) {
            int l = 24 + i;
            h0[i] = row[l * VV + lane];
            h1[i] = row[l * VV + 32 + lane];
            h2[i] = (lane < 16) ? row[l * VV + 64 + lane] : 0.f;
        }
    }
    if (l_use > 16) {                         // round 2
        #pragma unroll
        for (int i = 0; i < 8; ++i) {
            float p = s_phi[wrow][16 + i];
            a0 = fmaf(p, f0[i], a0); a1 = fmaf(p, f1[i], a1); a2 = fmaf(p, f2[i], a2);
        }
    }
    if (l_use > 24) {                         // round 3
        #pragma unroll
        for (int i = 0; i < 8; ++i) {
            float p = s_phi[wrow][24 + i];
            a0 = fmaf(p, h0[i], a0); a1 = fmaf(p, h1[i], a1); a2 = fmaf(p, h2[i], a2);
        }
    }

    // ---- rare tail windows, handled in-warp ----
    for (int lo = 32; lo < l_hi; lo += 32) {
        const int lu = min(l_hi, lo + 32);
        __syncwarp();
        float p2 = 0.f;
        if (lo + lane < lu) {
            float u = (float)(lo + lane + 1);
            #pragma unroll
            for (int k = 0; k < KK; ++k) {
                float a  = s_abk[wrow][k];
                float bb = s_abk[wrow][10 + k];
                float kk = s_abk[wrow][20 + k];
                float dv = kk - u;
                float e  = fmaxf(-bb * dv * dv, -50.f);
                p2 = fmaf(a, fast_exp_neg(e), p2);
            }
        }
        s_phi[wrow][lane] = p2;
        __syncwarp();

        #pragma unroll
        for (int r = 0; r < 4; ++r) {
            const int base = lo + r * 8;
            if (base < lu) {                  // ll <= lo+31 < 256: in-bounds
                #pragma unroll
                for (int i = 0; i < 8; ++i) {
                    int ll = base + i;
                    float p = s_phi[wrow][r * 8 + i];   // zero-padded beyond lu
                    a0 = fmaf(p, row[ll * VV + lane], a0);
                    a1 = fmaf(p, row[ll * VV + 32 + lane], a1);
                    if (lane < 16) a2 = fmaf(p, row[ll * VV + 64 + lane], a2);
                }
            }
        }
    }

    out_w[(size_t)b * VV + lane]      = a0;
    out_w[(size_t)b * VV + 32 + lane] = a1;
    if (lane < 16)
        out_w[(size_t)b * VV + 64 + lane] = a2;
}

extern "C" void kernel_launch(void* const* d_in, const int* in_sizes, int n_in,
                              void* d_out, int out_size) {
    const float* X          = (const float*)d_in[0];   // [B, D]
    const float* prev_kappa = (const float*)d_in[1];   // [B, K]
    const float* oh         = (const float*)d_in[2];   // [B, L, V]
    const int*   seqlens    = (const int*)  d_in[3];   // [B]
    const float* W          = (const float*)d_in[4];   // [D, 3K]
    const float* bias       = (const float*)d_in[5];   // [3K]
    const float* ks         = (const float*)d_in[6];   // scalar

    float* out       = (float*)d_out;
    float* out_w     = out;              // [B, V]
    float* out_kappa = out + BQ * VV;    // [B, K]

    gemm_act_kernel<<<128, 256>>>(X, W, bias, prev_kappa, ks, out_kappa);
    phi_w_kernel<<<BQ / 4, 128>>>(oh, seqlens, out_w);
}

// round 16
// speedup vs baseline: 1.0721x; 1.0721x over previous
#include <cuda_runtime.h>

// Problem constants (from reference): B=4096, D=512, K=10, L=256, V=80
#define BQ 4096
#define DD 512
#define KK 10
#define LL 256
#define VV 80

// Scratch: alpha[0:10], beta[10:20], kappa[20:30] per batch row.
__device__ float g_abk[BQ * 30];

// exp(e) for e <= 0 (clipped upstream), FMA-pipe only (no MUFU).
__device__ __forceinline__ float fast_exp_neg(float e) {
    float t = e * 1.44269504088896341f;
    int i = __float2int_rd(t);
    float f = t - (float)i;
    float p = 1.5403530393381610e-4f;
    p = fmaf(p, f, 1.3333558146428443e-3f);
    p = fmaf(p, f, 9.6181291076284772e-3f);
    p = fmaf(p, f, 5.5504108664821580e-2f);
    p = fmaf(p, f, 2.4022650695910071e-1f);
    p = fmaf(p, f, 6.9314718055994531e-1f);
    p = fmaf(p, f, 1.0f);
    return p * __int_as_float((i + 127) << 23);
}

__device__ __forceinline__ float warp_max(float v) {
    #pragma unroll
    for (int off = 16; off > 0; off >>= 1)
        v = fmaxf(v, __shfl_xor_sync(0xffffffffu, v, off));
    return v;
}

// Kernel A (R10's wall-clock-best config): raw = X@W + b, activations, kappa
// out + abk scratch. 256 blocks x 256 threads; block = 16 rows; warp w owns
// rows 2w,2w+1. W tile stride-33 => conflict-free LDS across lanes.
__global__ __launch_bounds__(256) void gemm_act_kernel(
    const float* __restrict__ X, const float* __restrict__ W,
    const float* __restrict__ bias, const float* __restrict__ prev_kappa,
    const float* __restrict__ kappa_scale_p, float* __restrict__ out_kappa)
{
    __shared__ float4 Xs4[16 * 32];          // 8 KB
    __shared__ float  Wsh[128 * 33];         // 16.5 KB, stride-33 padded

    const int tid  = threadIdx.x;
    const int warp = tid >> 5;
    const int lane = tid & 31;
    const int b0   = blockIdx.x * 16;

    const float4* X4 = (const float4*)X;

    float acc[2] = {0.f, 0.f};

    for (int t = 0; t < 4; ++t) {
        __syncthreads();
        for (int i = tid; i < 128 * 30; i += 256) {
            int d = i / 30, j = i - d * 30;
            Wsh[d * 33 + j] = W[t * (128 * 30) + i];
        }
        for (int i = tid; i < 512; i += 256) {
            int r = i >> 5, c = i & 31;
            Xs4[i] = X4[(size_t)(b0 + r) * 128 + t * 32 + c];
        }
        __syncthreads();

        const float4* xr0 = &Xs4[(warp * 2 + 0) * 32];
        const float4* xr1 = &Xs4[(warp * 2 + 1) * 32];

        #pragma unroll 8
        for (int c = 0; c < 32; ++c) {
            float w0 = Wsh[(4 * c + 0) * 33 + lane];
            float w1 = Wsh[(4 * c + 1) * 33 + lane];
            float w2 = Wsh[(4 * c + 2) * 33 + lane];
            float w3 = Wsh[(4 * c + 3) * 33 + lane];
            float4 x0 = xr0[c], x1 = xr1[c];
            acc[0] = fmaf(x0.x, w0, fmaf(x0.y, w1, fmaf(x0.z, w2, fmaf(x0.w, w3, acc[0]))));
            acc[1] = fmaf(x1.x, w0, fmaf(x1.y, w1, fmaf(x1.z, w2, fmaf(x1.w, w3, acc[1]))));
        }
    }

    if (lane < 30) {
        const float bj = bias[lane];
        const float ks = *kappa_scale_p;
        #pragma unroll
        for (int rr = 0; rr < 2; ++rr) {
            int b = b0 + warp * 2 + rr;
            float raw = acc[rr] + bj;
            float val;
            if (lane < 20) {
                val = __expf(fminf(fmaxf(raw, -8.f), 8.f));
            } else {
                float dk = __expf(fminf(fmaxf(raw + ks, -8.f), 5.f));
                val = prev_kappa[b * KK + (lane - 20)] + dk;
                out_kappa[b * KK + (lane - 20)] = val;
            }
            g_abk[b * 30 + lane] = val;
        }
    }
}

// Kernel B: 512 blocks x 256 threads, 8 rows/block, warp-per-row for the
// bounded first window (l <= 32, prefetched rounds), then BLOCK-LOCAL TAIL
// WORK-SHARING: tail windows (row, lo) of all 8 rows go into a shared list
// and all 8 warps work-steal them, accumulating into s_acc via smem atomics.
// R15 bug fix: __syncthreads() after counter init, BEFORE any warp's
// atomicAdd on s_ntail (warps race otherwise -> OOB s_tail index).
__global__ __launch_bounds__(256) void phi_w_kernel(
    const float* __restrict__ oh, const int* __restrict__ seqlens,
    float* __restrict__ out_w)
{
    __shared__ float s_abk[8][30];
    __shared__ float s_phi[8][36];     // per-WARP phi scratch
    __shared__ float s_acc[8][80];     // per-row accumulators
    __shared__ int   s_lhi[8];
    __shared__ int   s_tail[56][2];    // (rloc, lo) items, max 8*7
    __shared__ int   s_ntail, s_fetch;

    const int tid  = threadIdx.x;
    const int warp = tid >> 5;
    const int lane = tid & 31;
    const int b    = blockIdx.x * 8 + warp;

    if (tid == 0) { s_ntail = 0; s_fetch = 0; }
    __syncthreads();                   // counters visible before any atomicAdd

    const float* row = oh + (size_t)b * (LL * VV);

    // ---- front batch of independent loads ----
    float val = 0.f;
    if (lane < 30) val = g_abk[b * 30 + lane];
    const int seqlen = seqlens[b];

    float f0[8], f1[8], f2[8], h0[8], h1[8], h2[8];
    #pragma unroll
    for (int i = 0; i < 8; ++i) {            // rounds 0-1: always-valid memory
        f0[i] = row[i * VV + lane];
        f1[i] = row[i * VV + 32 + lane];
        f2[i] = (lane < 16) ? row[i * VV + 64 + lane] : 0.f;
    }
    #pragma unroll
    for (int i = 0; i < 8; ++i) {
        int l = 8 + i;
        h0[i] = row[l * VV + lane];
        h1[i] = row[l * VV + 32 + lane];
        h2[i] = (lane < 16) ? row[l * VV + 64 + lane] : 0.f;
    }

    if (lane < 30) s_abk[warp][lane] = val;

    // params via shuffles off the single abk load (valid where lane < 10)
    const float al = val;
    const float be = __shfl_sync(0xffffffffu, val, (lane + 10) & 31);
    const float ka = __shfl_sync(0xffffffffu, val, (lane + 20) & 31);

    // ---- analytic truncation bound (hidden under the prefetch latency) ----
    float pk = 0.f;
    if (lane < 10) {
        float ustar = fminf(fmaxf(rintf(ka), 1.f), (float)seqlen);
        float d = ka - ustar;
        pk = al * __expf(fmaxf(-be * d * d, -87.f));
    }
    const float pm = warp_max(pk);
    float lk = 0.f;
    if (lane < 10) {
        float theta = pm * 1e-8f;
        float lnr = __logf(al) - __logf(theta);   // theta->0 => +inf => full length
        lk = ka + sqrtf(fmaxf(lnr, 0.f) / be);
        lk = fminf(lk, 256.f);
    }
    const float lm = warp_max(lk);
    const int l_hi  = min((int)ceilf(lm), seqlen);
    const int l_use = min(l_hi, 32);
    if (lane == 0) {
        s_lhi[warp] = l_hi;
        for (int lo = 32; lo < l_hi; lo += 32) {
            int idx = atomicAdd(&s_ntail, 1);
            s_tail[idx][0] = warp;
            s_tail[idx][1] = lo;
        }
    }
    __syncwarp();

    // ---- phi[lane] for the first window (zero-padded beyond l_use) ----
    float ph = 0.f;
    if (lane < l_use) {
        float u = (float)(lane + 1);
        #pragma unroll
        for (int k = 0; k < KK; ++k) {
            float a  = s_abk[warp][k];
            float bb = s_abk[warp][10 + k];
            float kk = s_abk[warp][20 + k];
            float dv = kk - u;
            float e  = fmaxf(-bb * dv * dv, -50.f);
            ph = fmaf(a, fast_exp_neg(e), ph);
        }
    }
    s_phi[warp][lane] = ph;
    __syncwarp();

    float a0 = 0.f, a1 = 0.f, a2 = 0.f;

    // round 0 (l_hi >= 1 always)
    #pragma unroll
    for (int i = 0; i < 8; ++i) {
        float p = s_phi[warp][i];
        a0 = fmaf(p, f0[i], a0); a1 = fmaf(p, f1[i], a1); a2 = fmaf(p, f2[i], a2);
    }
    if (l_use > 16) {                         // reload f <- l 16..23
        #pragma unroll
        for (int i = 0; i < 8; ++i) {
            int l = 16 + i;
            f0[i] = row[l * VV + lane];
            f1[i] = row[l * VV + 32 + lane];
            f2[i] = (lane < 16) ? row[l * VV + 64 + lane] : 0.f;
        }
    }
    if (l_use > 8) {                          // round 1
        #pragma unroll
        for (int i = 0; i < 8; ++i) {
            float p = s_phi[warp][8 + i];
            a0 = fmaf(p, h0[i], a0); a1 = fmaf(p, h1[i], a1); a2 = fmaf(p, h2[i], a2);
        }
    }
    if (l_use > 24) {                         // reload h <- l 24..31
        #pragma unroll
        for (int i = 0; i < 8; ++i) {
            int l = 24 + i;
            h0[i] = row[l * VV + lane];
            h1[i] = row[l * VV + 32 + lane];
            h2[i] = (lane < 16) ? row[l * VV + 64 + lane] : 0.f;
        }
    }
    if (l_use > 16) {                         // round 2
        #pragma unroll
        for (int i = 0; i < 8; ++i) {
            float p = s_phi[warp][16 + i];
            a0 = fmaf(p, f0[i], a0); a1 = fmaf(p, f1[i], a1); a2 = fmaf(p, f2[i], a2);
        }
    }
    if (l_use > 24) {                         // round 3
        #pragma unroll
        for (int i = 0; i < 8; ++i) {
            float p = s_phi[warp][24 + i];
            a0 = fmaf(p, h0[i], a0); a1 = fmaf(p, h1[i], a1); a2 = fmaf(p, h2[i], a2);
        }
    }

    // deposit bounded-phase partials
    s_acc[warp][lane]      = a0;
    s_acc[warp][32 + lane] = a1;
    if (lane < 16) s_acc[warp][64 + lane] = a2;

    __syncthreads();

    // ---- tail work-sharing across all 8 warps ----
    const int ntail = s_ntail;
    for (;;) {
        int it = 0;
        if (lane == 0) it = atomicAdd(&s_fetch, 1);
        it = __shfl_sync(0xffffffffu, it, 0);
        if (it >= ntail) break;

        const int r  = s_tail[it][0];
        const int lo = s_tail[it][1];
        const int lu = min(s_lhi[r], lo + 32);
        const float* trow = oh + (size_t)(blockIdx.x * 8 + r) * (LL * VV);

        float p2 = 0.f;
        if (lo + lane < lu) {
            float u = (float)(lo + lane + 1);
            #pragma unroll
            for (int k = 0; k < KK; ++k) {
                float a  = s_abk[r][k];
                float bb = s_abk[r][10 + k];
                float kk = s_abk[r][20 + k];
                float dv = kk - u;
                float e  = fmaxf(-bb * dv * dv, -50.f);
                p2 = fmaf(a, fast_exp_neg(e), p2);
            }
        }
        s_phi[warp][lane] = p2;
        __syncwarp();

        float t0 = 0.f, t1 = 0.f, t2 = 0.f;
        #pragma unroll
        for (int rr = 0; rr < 4; ++rr) {
            const int base = lo + rr * 8;
            if (base < lu) {                  // ll <= lo+31 < 256: in-bounds
                #pragma unroll
                for (int i = 0; i < 8; ++i) {
                    int ll = base + i;
                    float p = s_phi[warp][rr * 8 + i];   // zero-padded beyond lu
                    t0 = fmaf(p, trow[ll * VV + lane], t0);
                    t1 = fmaf(p, trow[ll * VV + 32 + lane], t1);
                    if (lane < 16) t2 = fmaf(p, trow[ll * VV + 64 + lane], t2);
                }
            }
        }
        atomicAdd(&s_acc[r][lane],      t0);
        atomicAdd(&s_acc[r][32 + lane], t1);
        if (lane < 16) atomicAdd(&s_acc[r][64 + lane], t2);
    }

    __syncthreads();

    // ---- writeback: warp w writes its row ----
    out_w[(size_t)b * VV + lane]      = s_acc[warp][lane];
    out_w[(size_t)b * VV + 32 + lane] = s_acc[warp][32 + lane];
    if (lane < 16)
        out_w[(size_t)b * VV + 64 + lane] = s_acc[warp][64 + lane];
}

extern "C" void kernel_launch(void* const* d_in, const int* in_sizes, int n_in,
                              void* d_out, int out_size) {
    const float* X          = (const float*)d_in[0];   // [B, D]
    const float* prev_kappa = (const float*)d_in[1];   // [B, K]
    const float* oh         = (const float*)d_in[2];   // [B, L, V]
    const int*   seqlens    = (const int*)  d_in[3];   // [B]
    const float* W          = (const float*)d_in[4];   // [D, 3K]
    const float* bias       = (const float*)d_in[5];   // [3K]
    const float* ks         = (const float*)d_in[6];   // scalar

    float* out       = (float*)d_out;
    float* out_w     = out;              // [B, V]
    float* out_kappa = out + BQ * VV;    // [B, K]

    gemm_act_kernel<<<256, 256>>>(X, W, bias, prev_kappa, ks, out_kappa);
    phi_w_kernel<<<BQ / 8, 256>>>(oh, seqlens, out_w);
}

// round 17
// speedup vs baseline: 1.1745x; 1.0956x over previous
#include <cuda_runtime.h>

// Problem constants (from reference): B=4096, D=512, K=10, L=256, V=80
#define BQ 4096
#define DD 512
#define KK 10
#define LL 256
#define VV 80

// Split-K partial sums: g_raw[half][b][30]
__device__ float g_raw[2 * BQ * 30];

// exp(e) for e <= 0 (clipped upstream), FMA-pipe only (no MUFU).
__device__ __forceinline__ float fast_exp_neg(float e) {
    float t = e * 1.44269504088896341f;
    int i = __float2int_rd(t);
    float f = t - (float)i;
    float p = 1.5403530393381610e-4f;
    p = fmaf(p, f, 1.3333558146428443e-3f);
    p = fmaf(p, f, 9.6181291076284772e-3f);
    p = fmaf(p, f, 5.5504108664821580e-2f);
    p = fmaf(p, f, 2.4022650695910071e-1f);
    p = fmaf(p, f, 6.9314718055994531e-1f);
    p = fmaf(p, f, 1.0f);
    return p * __int_as_float((i + 127) << 23);
}

__device__ __forceinline__ float warp_max(float v) {
    #pragma unroll
    for (int off = 16; off > 0; off >>= 1)
        v = fmaxf(v, __shfl_xor_sync(0xffffffffu, v, off));
    return v;
}

// Kernel A (split-K): 512 blocks x 256 threads. Block = 16 rows x half of D
// (2 tiles of 128 d). Doubles CTAs/SM vs R10 (1.7 -> 3.46) and halves per-warp
// issue work -> latency exposure collapses. Partial sums to g_raw; activations
// deferred to kernel B's load front.
__global__ __launch_bounds__(256) void gemm_half_kernel(
    const float* __restrict__ X, const float* __restrict__ W)
{
    __shared__ float4 Xs4[16 * 32];          // 8 KB
    __shared__ float  Wsh[128 * 33];         // 16.5 KB, stride-33 padded

    const int tid  = threadIdx.x;
    const int warp = tid >> 5;
    const int lane = tid & 31;
    const int half = blockIdx.x & 1;
    const int b0   = (blockIdx.x >> 1) * 16;

    const float4* X4 = (const float4*)X;

    float acc[2] = {0.f, 0.f};

    for (int t = 0; t < 2; ++t) {
        const int dbase = half * 256 + t * 128;     // in floats
        __syncthreads();
        for (int i = tid; i < 128 * 30; i += 256) {
            int d = i / 30, j = i - d * 30;
            Wsh[d * 33 + j] = W[dbase * 30 + i];
        }
        for (int i = tid; i < 512; i += 256) {
            int r = i >> 5, c = i & 31;
            Xs4[i] = X4[(size_t)(b0 + r) * 128 + (dbase >> 2) + c];
        }
        __syncthreads();

        const float4* xr0 = &Xs4[(warp * 2 + 0) * 32];
        const float4* xr1 = &Xs4[(warp * 2 + 1) * 32];

        #pragma unroll 8
        for (int c = 0; c < 32; ++c) {
            float w0 = Wsh[(4 * c + 0) * 33 + lane];
            float w1 = Wsh[(4 * c + 1) * 33 + lane];
            float w2 = Wsh[(4 * c + 2) * 33 + lane];
            float w3 = Wsh[(4 * c + 3) * 33 + lane];
            float4 x0 = xr0[c], x1 = xr1[c];
            acc[0] = fmaf(x0.x, w0, fmaf(x0.y, w1, fmaf(x0.z, w2, fmaf(x0.w, w3, acc[0]))));
            acc[1] = fmaf(x1.x, w0, fmaf(x1.y, w1, fmaf(x1.z, w2, fmaf(x1.w, w3, acc[1]))));
        }
    }

    if (lane < 30) {
        #pragma unroll
        for (int rr = 0; rr < 2; ++rr) {
            int b = b0 + warp * 2 + rr;
            g_raw[half * (BQ * 30) + b * 30 + lane] = acc[rr];
        }
    }
}

// Kernel B: 512 blocks x 256 threads, 8 rows/block. Front phase now ALSO does
// the activations (r0+r1+bias -> exp clips -> alpha/beta/kappa + out_kappa),
// hidden under the one-hot prefetch latency. Then warp-per-row bounded window
// + block-local tail work-sharing with smem-atomic accumulation (R16 design).
__global__ __launch_bounds__(256) void phi_w_kernel(
    const float* __restrict__ oh, const int* __restrict__ seqlens,
    const float* __restrict__ bias, const float* __restrict__ prev_kappa,
    const float* __restrict__ kappa_scale_p,
    float* __restrict__ out_w, float* __restrict__ out_kappa)
{
    __shared__ float s_abk[8][30];
    __shared__ float s_phi[8][36];     // per-WARP phi scratch
    __shared__ float s_acc[8][80];     // per-row accumulators
    __shared__ int   s_lhi[8];
    __shared__ int   s_tail[56][2];    // (rloc, lo) items, max 8*7
    __shared__ int   s_ntail, s_fetch;

    const int tid  = threadIdx.x;
    const int warp = tid >> 5;
    const int lane = tid & 31;
    const int b    = blockIdx.x * 8 + warp;

    if (tid == 0) { s_ntail = 0; s_fetch = 0; }
    __syncthreads();                   // counters visible before any atomicAdd

    const float* row = oh + (size_t)b * (LL * VV);

    // ---- front batch of independent loads ----
    float r0 = 0.f, r1 = 0.f, bj = 0.f, pkap = 0.f;
    if (lane < 30) {
        r0 = g_raw[b * 30 + lane];
        r1 = g_raw[BQ * 30 + b * 30 + lane];
        bj = bias[lane];
    }
    if (lane >= 20 && lane < 30)
        pkap = prev_kappa[b * KK + (lane - 20)];
    const float ks = *kappa_scale_p;
    const int seqlen = seqlens[b];

    float f0[8], f1[8], f2[8], h0[8], h1[8], h2[8];
    #pragma unroll
    for (int i = 0; i < 8; ++i) {            // rounds 0-1: always-valid memory
        f0[i] = row[i * VV + lane];
        f1[i] = row[i * VV + 32 + lane];
        f2[i] = (lane < 16) ? row[i * VV + 64 + lane] : 0.f;
    }
    #pragma unroll
    for (int i = 0; i < 8; ++i) {
        int l = 8 + i;
        h0[i] = row[l * VV + lane];
        h1[i] = row[l * VV + 32 + lane];
        h2[i] = (lane < 16) ? row[l * VV + 64 + lane] : 0.f;
    }

    // ---- activations (moved from old kernel A) ----
    const float raw = r0 + r1 + bj;
    float val = 0.f;
    if (lane < 20) {
        val = __expf(fminf(fmaxf(raw, -8.f), 8.f));
    } else if (lane < 30) {
        float dk = __expf(fminf(fmaxf(raw + ks, -8.f), 5.f));
        val = pkap + dk;
        out_kappa[b * KK + (lane - 20)] = val;
    }
    if (lane < 30) s_abk[warp][lane] = val;

    // params via shuffles (valid where lane < 10)
    const float al = val;
    const float be = __shfl_sync(0xffffffffu, val, (lane + 10) & 31);
    const float ka = __shfl_sync(0xffffffffu, val, (lane + 20) & 31);

    // ---- analytic truncation bound ----
    float pk = 0.f;
    if (lane < 10) {
        float ustar = fminf(fmaxf(rintf(ka), 1.f), (float)seqlen);
        float d = ka - ustar;
        pk = al * __expf(fmaxf(-be * d * d, -87.f));
    }
    const float pm = warp_max(pk);
    float lk = 0.f;
    if (lane < 10) {
        float theta = pm * 1e-8f;
        float lnr = __logf(al) - __logf(theta);   // theta->0 => +inf => full length
        lk = ka + sqrtf(fmaxf(lnr, 0.f) / be);
        lk = fminf(lk, 256.f);
    }
    const float lm = warp_max(lk);
    const int l_hi  = min((int)ceilf(lm), seqlen);
    const int l_use = min(l_hi, 32);
    if (lane == 0) {
        s_lhi[warp] = l_hi;
        for (int lo = 32; lo < l_hi; lo += 32) {
            int idx = atomicAdd(&s_ntail, 1);
            s_tail[idx][0] = warp;
            s_tail[idx][1] = lo;
        }
    }
    __syncwarp();

    // ---- phi[lane] for the first window (zero-padded beyond l_use) ----
    float ph = 0.f;
    if (lane < l_use) {
        float u = (float)(lane + 1);
        #pragma unroll
        for (int k = 0; k < KK; ++k) {
            float a  = s_abk[warp][k];
            float bb = s_abk[warp][10 + k];
            float kk = s_abk[warp][20 + k];
            float dv = kk - u;
            float e  = fmaxf(-bb * dv * dv, -50.f);
            ph = fmaf(a, fast_exp_neg(e), ph);
        }
    }
    s_phi[warp][lane] = ph;
    __syncwarp();

    float a0 = 0.f, a1 = 0.f, a2 = 0.f;

    // round 0 (l_hi >= 1 always)
    #pragma unroll
    for (int i = 0; i < 8; ++i) {
        float p = s_phi[warp][i];
        a0 = fmaf(p, f0[i], a0); a1 = fmaf(p, f1[i], a1); a2 = fmaf(p, f2[i], a2);
    }
    if (l_use > 16) {                         // reload f <- l 16..23
        #pragma unroll
        for (int i = 0; i < 8; ++i) {
            int l = 16 + i;
            f0[i] = row[l * VV + lane];
            f1[i] = row[l * VV + 32 + lane];
            f2[i] = (lane < 16) ? row[l * VV + 64 + lane] : 0.f;
        }
    }
    if (l_use > 8) {                          // round 1
        #pragma unroll
        for (int i = 0; i < 8; ++i) {
            float p = s_phi[warp][8 + i];
            a0 = fmaf(p, h0[i], a0); a1 = fmaf(p, h1[i], a1); a2 = fmaf(p, h2[i], a2);
        }
    }
    if (l_use > 24) {                         // reload h <- l 24..31
        #pragma unroll
        for (int i = 0; i < 8; ++i) {
            int l = 24 + i;
            h0[i] = row[l * VV + lane];
            h1[i] = row[l * VV + 32 + lane];
            h2[i] = (lane < 16) ? row[l * VV + 64 + lane] : 0.f;
        }
    }
    if (l_use > 16) {                         // round 2
        #pragma unroll
        for (int i = 0; i < 8; ++i) {
            float p = s_phi[warp][16 + i];
            a0 = fmaf(p, f0[i], a0); a1 = fmaf(p, f1[i], a1); a2 = fmaf(p, f2[i], a2);
        }
    }
    if (l_use > 24) {                         // round 3
        #pragma unroll
        for (int i = 0; i < 8; ++i) {
            float p = s_phi[warp][24 + i];
            a0 = fmaf(p, h0[i], a0); a1 = fmaf(p, h1[i], a1); a2 = fmaf(p, h2[i], a2);
        }
    }

    // deposit bounded-phase partials
    s_acc[warp][lane]      = a0;
    s_acc[warp][32 + lane] = a1;
    if (lane < 16) s_acc[warp][64 + lane] = a2;

    __syncthreads();

    // ---- tail work-sharing across all 8 warps ----
    const int ntail = s_ntail;
    for (;;) {
        int it = 0;
        if (lane == 0) it = atomicAdd(&s_fetch, 1);
        it = __shfl_sync(0xffffffffu, it, 0);
        if (it >= ntail) break;

        const int r  = s_tail[it][0];
        const int lo = s_tail[it][1];
        const int lu = min(s_lhi[r], lo + 32);
        const float* trow = oh + (size_t)(blockIdx.x * 8 + r) * (LL * VV);

        float p2 = 0.f;
        if (lo + lane < lu) {
            float u = (float)(lo + lane + 1);
            #pragma unroll
            for (int k = 0; k < KK; ++k) {
                float a  = s_abk[r][k];
                float bb = s_abk[r][10 + k];
                float kk = s_abk[r][20 + k];
                float dv = kk - u;
                float e  = fmaxf(-bb * dv * dv, -50.f);
                p2 = fmaf(a, fast_exp_neg(e), p2);
            }
        }
        s_phi[warp][lane] = p2;
        __syncwarp();

        float t0 = 0.f, t1 = 0.f, t2 = 0.f;
        #pragma unroll
        for (int rr = 0; rr < 4; ++rr) {
            const int base = lo + rr * 8;
            if (base < lu) {                  // ll <= lo+31 < 256: in-bounds
                #pragma unroll
                for (int i = 0; i < 8; ++i) {
                    int ll = base + i;
                    float p = s_phi[warp][rr * 8 + i];   // zero-padded beyond lu
                    t0 = fmaf(p, trow[ll * VV + lane], t0);
                    t1 = fmaf(p, trow[ll * VV + 32 + lane], t1);
                    if (lane < 16) t2 = fmaf(p, trow[ll * VV + 64 + lane], t2);
                }
            }
        }
        atomicAdd(&s_acc[r][lane],      t0);
        atomicAdd(&s_acc[r][32 + lane], t1);
        if (lane < 16) atomicAdd(&s_acc[r][64 + lane], t2);
    }

    __syncthreads();

    // ---- writeback: warp w writes its row ----
    out_w[(size_t)b * VV + lane]      = s_acc[warp][lane];
    out_w[(size_t)b * VV + 32 + lane] = s_acc[warp][32 + lane];
    if (lane < 16)
        out_w[(size_t)b * VV + 64 + lane] = s_acc[warp][64 + lane];
}

extern "C" void kernel_launch(void* const* d_in, const int* in_sizes, int n_in,
                              void* d_out, int out_size) {
    const float* X          = (const float*)d_in[0];   // [B, D]
    const float* prev_kappa = (const float*)d_in[1];   // [B, K]
    const float* oh         = (const float*)d_in[2];   // [B, L, V]
    const int*   seqlens    = (const int*)  d_in[3];   // [B]
    const float* W          = (const float*)d_in[4];   // [D, 3K]
    const float* bias       = (const float*)d_in[5];   // [3K]
    const float* ks         = (const float*)d_in[6];   // scalar

    float* out       = (float*)d_out;
    float* out_w     = out;              // [B, V]
    float* out_kappa = out + BQ * VV;    // [B, K]

    gemm_half_kernel<<<512, 256>>>(X, W);
    phi_w_kernel<<<BQ / 8, 256>>>(oh, seqlens, bias, prev_kappa, ks,
                                  out_w, out_kappa);
}